// round 10
// baseline (speedup 1.0000x reference)
#include <cuda_runtime.h>
#include <math.h>
#include <math_constants.h>

#define THREADS 256
#define NBUCKET 32
#define MAXB 32768
#define MAXG 1024
#define MAXROWS 80        // max rows per block = ceil(MAXB / G)

__device__ float g_part[MAXG][32];   // per-block partials: [0..15] soft, [16..31] hard
__device__ int   g_ctr = 0;          // finish counter (reset by last block)

// ---- fallback-path globals (non-E16 shapes) ----
__device__ float g_acc[NBUCKET][64];

__global__ void init_acc_kernel() {
    g_acc[blockIdx.x][threadIdx.x] = 0.f;   // <<<NBUCKET, 64>>>
}

__global__ void finalize_kernel(float* __restrict__ out_tail, float invB, int E) {
    int t = threadIdx.x;
    if (t < 2 * E) {
        int idx = (t < E) ? t : (32 + (t - E));
        float s = 0.f;
        #pragma unroll
        for (int b = 0; b < NBUCKET; b++) s += g_acc[b][idx];
        out_tail[t] = s * invB;
    }
}

// ---------------------------------------------------------------------------
// Single fused persistent kernel. E == 16, DIN % 32 == 0, DIN <= 512.
// ---------------------------------------------------------------------------
__global__ __launch_bounds__(THREADS) void moe16_kernel(
    const float* __restrict__ f, const float* __restrict__ x,
    const float* __restrict__ perm, const float* __restrict__ gate,
    const float* __restrict__ bias, float* __restrict__ y,
    int B, int D, int DIN, int P, int do_tail)
{
    constexpr int E = 16;
    __shared__ float gs[E * 513];          // padded gate rows (conflict-free columns)
    __shared__ float pw[E * E];
    __shared__ float bs[E];
    __shared__ float sgp[MAXROWS * 16];    // per-local-row normalized gates
    __shared__ float part[8][32];
    __shared__ int   last_flag;

    const int tid    = threadIdx.x;
    const int lane   = tid & 31;
    const int warpId = tid >> 5;
    const int G      = gridDim.x;
    const int nK     = DIN >> 5;

    // ---- Phase 0: stage gate / pw / bias ----
    for (int i = tid; i < E * DIN; i += THREADS) {
        int e = i / DIN, k = i - e * DIN;
        gs[e * 513 + k] = gate[i];
    }
    const float invP = 1.f / (float)P;
    for (int i = tid; i < E * E; i += THREADS) {
        float s = 0.f;
        for (int p = 0; p < P; p++) s += perm[p * E * E + i];
        pw[i] = s * invP;
    }
    if (tid < E) bs[tid] = bias[tid];
    __syncthreads();

    // ---- Phase 1: gate this block's rows (warp per row) ----
    float partial = 0.f;
    for (int idx = warpId, b = blockIdx.x + warpId * G; b < B; idx += 8, b += 8 * G) {
        const float* xr = x + (size_t)b * DIN;
        float acc[E];
        #pragma unroll
        for (int e = 0; e < E; e++) acc[e] = 0.f;

        #pragma unroll 4
        for (int i = 0; i < nK; i++) {
            const int k = lane + (i << 5);
            const float xv = xr[k];                    // coalesced 128B
            const float* gcol = gs + k;
            #pragma unroll
            for (int e = 0; e < E; e++) acc[e] += xv * gcol[e * 513];
        }
        #pragma unroll
        for (int off = 16; off > 0; off >>= 1) {
            #pragma unroll
            for (int e = 0; e < E; e++)
                acc[e] += __shfl_xor_sync(0xffffffffu, acc[e], off);
        }
        #pragma unroll
        for (int e = 0; e < E; e++) acc[e] += bs[e];

        // top-2 -> faithful (==0 -> -inf) softmax -> permute -> normalize
        float v1 = -CUDART_INF_F; int i1 = 0;
        #pragma unroll
        for (int i = 0; i < E; i++) if (acc[i] > v1) { v1 = acc[i]; i1 = i; }
        float v2 = -CUDART_INF_F; int i2 = 0;
        #pragma unroll
        for (int i = 0; i < E; i++) if (i != i1 && acc[i] > v2) { v2 = acc[i]; i2 = i; }
        float m1 = (v1 == 0.f) ? -CUDART_INF_F : v1;
        float m2 = (v2 == 0.f) ? -CUDART_INF_F : v2;
        float m  = fmaxf(m1, m2);
        float e1 = __expf(m1 - m), e2 = __expf(m2 - m);
        float zi = 1.f / (e1 + e2);
        float g1 = e1 * zi, g2 = e2 * zi;
        float raw[E]; float s = 0.f;
        #pragma unroll
        for (int q = 0; q < E; q++) {
            raw[q] = g1 * pw[i1 * E + q] + g2 * pw[i2 * E + q];
            s += raw[q];
        }
        const float rinv = 1.f / s;

        const float val = raw[lane & 15] * rinv;
        if (lane < 16) {
            sgp[idx * 16 + lane] = val;
            partial += val;                               // soft partial
        } else {
            partial += (val < 1e-5f) ? 0.f : 1.f;         // hard partial
        }
    }
    part[warpId][lane] = partial;
    __syncthreads();
    if (tid < 32) {
        float s = 0.f;
        #pragma unroll
        for (int w = 0; w < 8; w++) s += part[w][tid];
        g_part[blockIdx.x][tid] = s;
    }

    // ---- Phase 2: stream this block's rows ----
    for (int idx = 0, b = blockIdx.x; b < B; idx++, b += G) {
        const float4* w4 = (const float4*)(sgp + idx * 16);
        const float4 w0 = w4[0], w1 = w4[1], w2 = w4[2], w3 = w4[3];
        const float4* fb = (const float4*)(f + (size_t)b * D * E);
        float* yr = y + (size_t)b * D;

        if (D == 2 * THREADS) {
            const int d0 = tid, d1 = tid + THREADS;
            const float4* p0 = fb + (size_t)d0 * 4;
            const float4* p1 = fb + (size_t)d1 * 4;
            float4 a0 = p0[0], a1 = p0[1], a2 = p0[2], a3 = p0[3];
            float4 c0 = p1[0], c1 = p1[1], c2 = p1[2], c3 = p1[3];
            float r0 = a0.x*w0.x + a0.y*w0.y + a0.z*w0.z + a0.w*w0.w
                     + a1.x*w1.x + a1.y*w1.y + a1.z*w1.z + a1.w*w1.w
                     + a2.x*w2.x + a2.y*w2.y + a2.z*w2.z + a2.w*w2.w
                     + a3.x*w3.x + a3.y*w3.y + a3.z*w3.z + a3.w*w3.w;
            float r1 = c0.x*w0.x + c0.y*w0.y + c0.z*w0.z + c0.w*w0.w
                     + c1.x*w1.x + c1.y*w1.y + c1.z*w1.z + c1.w*w1.w
                     + c2.x*w2.x + c2.y*w2.y + c2.z*w2.z + c2.w*w2.w
                     + c3.x*w3.x + c3.y*w3.y + c3.z*w3.z + c3.w*w3.w;
            yr[d0] = r0;
            yr[d1] = r1;
        } else {
            for (int d = tid; d < D; d += THREADS) {
                const float4* fr = fb + (size_t)d * 4;
                float4 a0 = fr[0], a1 = fr[1], a2 = fr[2], a3 = fr[3];
                float acc = a0.x*w0.x + a0.y*w0.y + a0.z*w0.z + a0.w*w0.w
                          + a1.x*w1.x + a1.y*w1.y + a1.z*w1.z + a1.w*w1.w
                          + a2.x*w2.x + a2.y*w2.y + a2.z*w2.z + a2.w*w2.w
                          + a3.x*w3.x + a3.y*w3.y + a3.z*w3.z + a3.w*w3.w;
                yr[d] = acc;
            }
        }
    }

    // ---- Phase 3: last block reduces partials and writes the tail ----
    __syncthreads();
    if (tid == 0) {
        __threadfence();
        int old = atomicAdd(&g_ctr, 1);
        last_flag = (old == G - 1) ? 1 : 0;
    }
    __syncthreads();
    if (last_flag) {
        __threadfence();
        float s = 0.f;
        for (int i = warpId; i < G; i += 8) s += g_part[i][lane];
        part[warpId][lane] = s;
        __syncthreads();
        if (tid < 32) {
            float tot = 0.f;
            #pragma unroll
            for (int w = 0; w < 8; w++) tot += part[w][tid];
            if (do_tail) {
                const float invB = 1.f / (float)B;
                // tid<16: soft avg; tid>=16: hard avg (fixed order -> deterministic)
                y[(size_t)B * D + tid] = tot * invB;
            }
        }
        if (tid == 0) g_ctr = 0;     // reset for next graph replay
    }
}

// ---------------------------------------------------------------------------
// Generic fallback (any E <= 32)
// ---------------------------------------------------------------------------
__global__ void fused_generic_kernel(
    const float* __restrict__ f, const float* __restrict__ x,
    const float* __restrict__ perm, const float* __restrict__ gate,
    const float* __restrict__ bias, float* __restrict__ y,
    int D, int DIN, int P, int E)
{
    extern __shared__ float smem[];
    float* xs     = smem;
    float* pw     = xs + DIN;
    float* logits = pw + E * E;
    float* gp     = logits + E;
    const int tid = threadIdx.x;
    const int b   = blockIdx.x;

    for (int k = tid; k < DIN; k += blockDim.x) xs[k] = x[(size_t)b * DIN + k];
    const float invP = 1.f / (float)P;
    for (int i = tid; i < E * E; i += blockDim.x) {
        float s = 0.f;
        for (int p = 0; p < P; p++) s += perm[p * E * E + i];
        pw[i] = s * invP;
    }
    __syncthreads();
    for (int e = tid; e < E; e += blockDim.x) {
        float s = 0.f;
        const float* gr = gate + (size_t)e * DIN;
        for (int k = 0; k < DIN; k++) s += xs[k] * gr[k];
        logits[e] = s + bias[e];
    }
    __syncthreads();
    if (tid == 0) {
        float v1 = -CUDART_INF_F; int i1 = 0;
        for (int i = 0; i < E; i++) if (logits[i] > v1) { v1 = logits[i]; i1 = i; }
        float v2 = -CUDART_INF_F; int i2 = 0;
        for (int i = 0; i < E; i++) if (i != i1 && logits[i] > v2) { v2 = logits[i]; i2 = i; }
        float m1 = (v1 == 0.f) ? -CUDART_INF_F : v1;
        float m2 = (v2 == 0.f) ? -CUDART_INF_F : v2;
        float m  = fmaxf(m1, m2);
        float e1 = __expf(m1 - m), e2 = __expf(m2 - m);
        float zi = 1.f / (e1 + e2);
        float g1 = e1 * zi, g2 = e2 * zi;
        float s = 0.f;
        for (int q = 0; q < E; q++) {
            float r = g1 * pw[i1 * E + q] + g2 * pw[i2 * E + q];
            gp[q] = r; s += r;
        }
        const float rinv = 1.f / s;
        const int bucket = b & (NBUCKET - 1);
        for (int q = 0; q < E; q++) {
            float v = gp[q] * rinv;
            gp[q] = v;
            if (q < 32) {
                atomicAdd(&g_acc[bucket][q], v);
                atomicAdd(&g_acc[bucket][32 + q], (v < 1e-5f) ? 0.f : 1.f);
            }
        }
    }
    __syncthreads();
    const size_t base = (size_t)b * D * E;
    for (int d = tid; d < D; d += blockDim.x) {
        const float* fr = f + base + (size_t)d * E;
        float acc = 0.f;
        for (int e = 0; e < E; e++) acc += fr[e] * gp[e];
        y[(size_t)b * D + d] = acc;
    }
}

extern "C" void kernel_launch(void* const* d_in, const int* in_sizes, int n_in,
                              void* d_out, int out_size) {
    const float* f    = (const float*)d_in[0];
    const float* x    = (const float*)d_in[1];
    const float* perm = (const float*)d_in[2];
    const float* gate = (const float*)d_in[3];
    const float* bias = (const float*)d_in[4];

    const int E   = in_sizes[4];
    const int DIN = in_sizes[3] / E;
    const int B   = in_sizes[1] / DIN;
    const int D   = (int)((long long)in_sizes[0] / ((long long)B * E));
    const int P   = in_sizes[2] / (E * E);
    float* y = (float*)d_out;

    const long long tail = (long long)B * D;
    const int do_tail = ((long long)out_size >= tail + 2LL * E) ? 1 : 0;

    if (E == 16 && DIN % 32 == 0 && DIN <= 512 && B <= MAXB) {
        int G = 444;                       // ~3 CTAs/SM persistent
        if (G > B) G = B;
        moe16_kernel<<<G, THREADS>>>(f, x, perm, gate, bias, y, B, D, DIN, P, do_tail);
    } else {
        init_acc_kernel<<<NBUCKET, 64>>>();
        const size_t smem = (size_t)(DIN + E * E + 2 * E + 8) * sizeof(float);
        fused_generic_kernel<<<B, THREADS, smem>>>(f, x, perm, gate, bias, y, D, DIN, P, E);
        if (do_tail)
            finalize_kernel<<<1, ((2 * E + 31) / 32) * 32>>>(y + tail, 1.f / (float)B, E);
    }
}

// round 11
// speedup vs baseline: 1.7568x; 1.7568x over previous
#include <cuda_runtime.h>
#include <math.h>
#include <math_constants.h>

#define THREADS 256
#define NBUCKET 32
#define MAXB 32768
#define MAXG 1024
#define MAXROWS 80

__device__ float g_part[MAXG][32];   // per-block partials: [0..15] soft, [16..31] hard
__device__ int   g_ctr = 0;

// ---- fallback-path globals ----
__device__ float g_acc[NBUCKET][64];

__global__ void init_acc_kernel() {
    g_acc[blockIdx.x][threadIdx.x] = 0.f;
}

__global__ void finalize_kernel(float* __restrict__ out_tail, float invB, int E) {
    int t = threadIdx.x;
    if (t < 2 * E) {
        int idx = (t < E) ? t : (32 + (t - E));
        float s = 0.f;
        #pragma unroll
        for (int b = 0; b < NBUCKET; b++) s += g_acc[b][idx];
        out_tail[t] = s * invB;
    }
}

// ---------------------------------------------------------------------------
// Single fused persistent kernel. E==16, DIN%32==0, DIN<=512, D%64==0.
// ---------------------------------------------------------------------------
__global__ __launch_bounds__(THREADS) void moe16_kernel(
    const float* __restrict__ f, const float* __restrict__ x,
    const float* __restrict__ perm, const float* __restrict__ gate,
    const float* __restrict__ bias, float* __restrict__ y,
    int B, int D, int DIN, int P, int do_tail)
{
    constexpr int E = 16;
    __shared__ float gs[E * 513];
    __shared__ float pw[E * E];
    __shared__ float bs[E];
    __shared__ float sgp[MAXROWS * 16];
    __shared__ float part[8][32];
    __shared__ int   last_flag;

    const int tid    = threadIdx.x;
    const int lane   = tid & 31;
    const int warpId = tid >> 5;
    const int G      = gridDim.x;
    const int nK     = DIN >> 5;

    // ---- Phase 0: stage gate / pw / bias ----
    for (int i = tid; i < E * DIN; i += THREADS) {
        int e = i / DIN, k = i - e * DIN;
        gs[e * 513 + k] = gate[i];
    }
    const float invP = 1.f / (float)P;
    for (int i = tid; i < E * E; i += THREADS) {
        float s = 0.f;
        for (int p = 0; p < P; p++) s += perm[p * E * E + i];
        pw[i] = s * invP;
    }
    if (tid < E) bs[tid] = bias[tid];
    __syncthreads();

    // ---- Phase 1: gate this block's rows (warp per row) ----
    float partial = 0.f;
    for (int idx = warpId, b = blockIdx.x + warpId * G; b < B; idx += 8, b += 8 * G) {
        const float* xr = x + (size_t)b * DIN;
        float acc[E];
        #pragma unroll
        for (int e = 0; e < E; e++) acc[e] = 0.f;

        #pragma unroll 4
        for (int i = 0; i < nK; i++) {
            const int k = lane + (i << 5);
            const float xv = xr[k];
            const float* gcol = gs + k;
            #pragma unroll
            for (int e = 0; e < E; e++) acc[e] += xv * gcol[e * 513];
        }
        #pragma unroll
        for (int off = 16; off > 0; off >>= 1) {
            #pragma unroll
            for (int e = 0; e < E; e++)
                acc[e] += __shfl_xor_sync(0xffffffffu, acc[e], off);
        }
        #pragma unroll
        for (int e = 0; e < E; e++) acc[e] += bs[e];

        float v1 = -CUDART_INF_F; int i1 = 0;
        #pragma unroll
        for (int i = 0; i < E; i++) if (acc[i] > v1) { v1 = acc[i]; i1 = i; }
        float v2 = -CUDART_INF_F; int i2 = 0;
        #pragma unroll
        for (int i = 0; i < E; i++) if (i != i1 && acc[i] > v2) { v2 = acc[i]; i2 = i; }
        float m1 = (v1 == 0.f) ? -CUDART_INF_F : v1;
        float m2 = (v2 == 0.f) ? -CUDART_INF_F : v2;
        float m  = fmaxf(m1, m2);
        float e1 = __expf(m1 - m), e2 = __expf(m2 - m);
        float zi = 1.f / (e1 + e2);
        float g1 = e1 * zi, g2 = e2 * zi;
        float raw[E]; float s = 0.f;
        #pragma unroll
        for (int q = 0; q < E; q++) {
            raw[q] = g1 * pw[i1 * E + q] + g2 * pw[i2 * E + q];
            s += raw[q];
        }
        const float rinv = 1.f / s;

        const float val = raw[lane & 15] * rinv;
        if (lane < 16) {
            sgp[idx * 16 + lane] = val;
            partial += val;
        } else {
            partial += (val < 1e-5f) ? 0.f : 1.f;
        }
    }
    part[warpId][lane] = partial;
    __syncthreads();
    if (tid < 32) {
        float s = 0.f;
        #pragma unroll
        for (int w = 0; w < 8; w++) s += part[w][tid];
        g_part[blockIdx.x][tid] = s;
    }

    // ---- Phase 2: stream rows. Quad-per-d: contiguous warp loads (4 wf/instr).
    // lane reads float4 #(s + j*32 + lane); its weight chunk is w[lane&3].
    const int dPerWarp = D >> 3;           // d-values per warp (D/8)
    for (int idx = 0, b = blockIdx.x; b < B; idx++, b += G) {
        const float4 wsel = ((const float4*)(sgp + idx * 16))[lane & 3];
        const float4* fw = (const float4*)(f + (size_t)b * D * E)
                           + (size_t)warpId * (D >> 1);   // warp's contiguous chunk
        float* yr = y + (size_t)b * D + warpId * dPerWarp;
        const int outLane = lane >> 2;
        const bool qlead = (lane & 3) == 0;

        if (D == 512) {                    // 8 iterations, loads front-batched
            float4 a[8];
            #pragma unroll
            for (int j = 0; j < 8; j++) a[j] = fw[j * 32 + lane];
            #pragma unroll
            for (int j = 0; j < 8; j++) {
                float p = a[j].x * wsel.x + a[j].y * wsel.y
                        + a[j].z * wsel.z + a[j].w * wsel.w;
                p += __shfl_xor_sync(0xffffffffu, p, 1);
                p += __shfl_xor_sync(0xffffffffu, p, 2);
                if (qlead) yr[j * 8 + outLane] = p;
            }
        } else {                           // generic D % 64 == 0
            const int nJ = dPerWarp >> 3;
            for (int j = 0; j < nJ; j++) {
                float4 a = fw[j * 32 + lane];
                float p = a.x * wsel.x + a.y * wsel.y + a.z * wsel.z + a.w * wsel.w;
                p += __shfl_xor_sync(0xffffffffu, p, 1);
                p += __shfl_xor_sync(0xffffffffu, p, 2);
                if (qlead) yr[j * 8 + outLane] = p;
            }
        }
    }

    // ---- Phase 3: last block reduces partials, writes tail ----
    __syncthreads();
    if (tid == 0) {
        __threadfence();
        int old = atomicAdd(&g_ctr, 1);
        last_flag = (old == G - 1) ? 1 : 0;
    }
    __syncthreads();
    if (last_flag) {
        __threadfence();
        float s = 0.f;
        for (int i = warpId; i < G; i += 8) s += g_part[i][lane];
        part[warpId][lane] = s;
        __syncthreads();
        if (tid < 32) {
            float tot = 0.f;
            #pragma unroll
            for (int w = 0; w < 8; w++) tot += part[w][tid];
            if (do_tail)
                y[(size_t)B * D + tid] = tot / (float)B;
        }
        if (tid == 0) g_ctr = 0;
    }
}

// ---------------------------------------------------------------------------
// Generic fallback (any E <= 32)
// ---------------------------------------------------------------------------
__global__ void fused_generic_kernel(
    const float* __restrict__ f, const float* __restrict__ x,
    const float* __restrict__ perm, const float* __restrict__ gate,
    const float* __restrict__ bias, float* __restrict__ y,
    int D, int DIN, int P, int E)
{
    extern __shared__ float smem[];
    float* xs     = smem;
    float* pw     = xs + DIN;
    float* logits = pw + E * E;
    float* gp     = logits + E;
    const int tid = threadIdx.x;
    const int b   = blockIdx.x;

    for (int k = tid; k < DIN; k += blockDim.x) xs[k] = x[(size_t)b * DIN + k];
    const float invP = 1.f / (float)P;
    for (int i = tid; i < E * E; i += blockDim.x) {
        float s = 0.f;
        for (int p = 0; p < P; p++) s += perm[p * E * E + i];
        pw[i] = s * invP;
    }
    __syncthreads();
    for (int e = tid; e < E; e += blockDim.x) {
        float s = 0.f;
        const float* gr = gate + (size_t)e * DIN;
        for (int k = 0; k < DIN; k++) s += xs[k] * gr[k];
        logits[e] = s + bias[e];
    }
    __syncthreads();
    if (tid == 0) {
        float v1 = -CUDART_INF_F; int i1 = 0;
        for (int i = 0; i < E; i++) if (logits[i] > v1) { v1 = logits[i]; i1 = i; }
        float v2 = -CUDART_INF_F; int i2 = 0;
        for (int i = 0; i < E; i++) if (i != i1 && logits[i] > v2) { v2 = logits[i]; i2 = i; }
        float m1 = (v1 == 0.f) ? -CUDART_INF_F : v1;
        float m2 = (v2 == 0.f) ? -CUDART_INF_F : v2;
        float m  = fmaxf(m1, m2);
        float e1 = __expf(m1 - m), e2 = __expf(m2 - m);
        float zi = 1.f / (e1 + e2);
        float g1 = e1 * zi, g2 = e2 * zi;
        float s = 0.f;
        for (int q = 0; q < E; q++) {
            float r = g1 * pw[i1 * E + q] + g2 * pw[i2 * E + q];
            gp[q] = r; s += r;
        }
        const float rinv = 1.f / s;
        const int bucket = b & (NBUCKET - 1);
        for (int q = 0; q < E; q++) {
            float v = gp[q] * rinv;
            gp[q] = v;
            if (q < 32) {
                atomicAdd(&g_acc[bucket][q], v);
                atomicAdd(&g_acc[bucket][32 + q], (v < 1e-5f) ? 0.f : 1.f);
            }
        }
    }
    __syncthreads();
    const size_t base = (size_t)b * D * E;
    for (int d = tid; d < D; d += blockDim.x) {
        const float* fr = f + base + (size_t)d * E;
        float acc = 0.f;
        for (int e = 0; e < E; e++) acc += fr[e] * gp[e];
        y[(size_t)b * D + d] = acc;
    }
}

extern "C" void kernel_launch(void* const* d_in, const int* in_sizes, int n_in,
                              void* d_out, int out_size) {
    const float* f    = (const float*)d_in[0];
    const float* x    = (const float*)d_in[1];
    const float* perm = (const float*)d_in[2];
    const float* gate = (const float*)d_in[3];
    const float* bias = (const float*)d_in[4];

    const int E   = in_sizes[4];
    const int DIN = in_sizes[3] / E;
    const int B   = in_sizes[1] / DIN;
    const int D   = (int)((long long)in_sizes[0] / ((long long)B * E));
    const int P   = in_sizes[2] / (E * E);
    float* y = (float*)d_out;

    const long long tail = (long long)B * D;
    const int do_tail = ((long long)out_size >= tail + 2LL * E) ? 1 : 0;

    if (E == 16 && DIN % 32 == 0 && DIN <= 512 && D % 64 == 0 && B <= MAXB) {
        int G = 592;                       // 4 CTAs/SM persistent
        if (G > B) G = B;
        if ((B + G - 1) / G > MAXROWS) G = (B + MAXROWS - 1) / MAXROWS;
        moe16_kernel<<<G, THREADS>>>(f, x, perm, gate, bias, y, B, D, DIN, P, do_tail);
    } else {
        init_acc_kernel<<<NBUCKET, 64>>>();
        const size_t smem = (size_t)(DIN + E * E + 2 * E + 8) * sizeof(float);
        fused_generic_kernel<<<B, THREADS, smem>>>(f, x, perm, gate, bias, y, D, DIN, P, E);
        if (do_tail)
            finalize_kernel<<<1, ((2 * E + 31) / 32) * 32>>>(y + tail, 1.f / (float)B, E);
    }
}